// round 14
// baseline (speedup 1.0000x reference)
#include <cuda_runtime.h>
#include <math.h>

// GRU recurrence, persistent kernel, round 11: KRH=44 via register diet +
// float2-vectorized gate + arrive/sync barrier split.
// B=256, T=2048, H=150 (3H=450 gate rows), I=O=1.
// 128 CTAs x 512 threads; CTA owns batches (2*cta, 2*cta+1).
// Two K-half groups of 256 threads: grp 0 k=0..75, grp 1 k=76..151.
// Warps 0-6 per group (lt<224): rows lt, lt+224. Warp 7: rows 448/449 + y-head.
// Per main thread: 44 W floats/row in regs (f32x2 pairs), 32/row in SMEM.
// Gate: threads lt<75 per group, 2 hidden units each (units 2u, 2u+1).

#define NTH     512
#define NGRP    256
#define HID     150
#define TLEN    2048
#define KH      76         // K per half (152 padded)
#define KRH     44         // reg W floats per half-row (22 u64)
#define NGR     11         // 4-float reg k-groups
#define NSM     8          // 4-float smem k-groups (32 floats)
#define NMROW   448

// SMEM layout (floats):
#define OFF_SW   0                          // float4 [16][448] = 28672
#define OFF_SX   28672                      // float2[2048] = 4096
#define OFF_H0   32768                      // 160
#define OFF_H1   32928                      // 160
#define OFF_PA   33088                      // float2[452] = 904
#define OFF_PB   33992                      // float2[452] = 904
#define OFF_Y0   34896                      // 160
#define OFF_Y1   35056                      // 160
#define OFF_BIA  35216                      // float2[452] = 904  (wih,bias)/row
#define OFF_GC   36120                      // float4[76] = 304  (win0,bin0,win1,bin1)
#define OFF_GW   36424                      // float2[76] = 152  (wlin pair)
#define OFF_BL   36576                      // 1
#define SMEM_FLOATS 36580                   // 146,320 B

typedef unsigned long long u64;

#define FFMA2(d, a, b) asm("fma.rn.f32x2 %0, %1, %2, %0;" : "+l"(d) : "l"(a), "l"(b))
#define BAR_SYNC(id)   asm volatile("bar.sync %0, %1;"   :: "n"(id), "n"(NTH) : "memory")
#define BAR_ARRIVE(id) asm volatile("bar.arrive %0, %1;" :: "n"(id), "n"(NTH) : "memory")

__device__ __forceinline__ u64 pack2(float a, float b) {
    u64 r; asm("mov.b64 %0, {%1, %2};" : "=l"(r) : "f"(a), "f"(b)); return r;
}
__device__ __forceinline__ float rsum2(u64 v) {
    float lo, hi; asm("mov.b64 {%0, %1}, %2;" : "=f"(lo), "=f"(hi) : "l"(v));
    return lo + hi;
}
__device__ __forceinline__ float tanha(float x) {       // MUFU.TANH
    float y; asm("tanh.approx.f32 %0, %1;" : "=f"(y) : "f"(x)); return y;
}
__device__ __forceinline__ float sigt(float v) {        // sigmoid via tanh.approx
    return fmaf(0.5f, tanha(0.5f * v), 0.5f);
}

extern "C" __global__ void __launch_bounds__(NTH, 1)
gru_persistent(const float* __restrict__ x,     // [B][T]
               const float* __restrict__ Wih,   // [450][1]
               const float* __restrict__ Whh,   // [450][150]
               const float* __restrict__ bih,   // [450]
               const float* __restrict__ bhh,   // [450]
               const float* __restrict__ Wlin,  // [1][150]
               const float* __restrict__ blin,  // [1]
               float* __restrict__ out)         // [B][T]
{
    extern __shared__ float smem[];
    float4* sW4  = (float4*)(smem + OFF_SW);
    float2* sxp  = (float2*)(smem + OFF_SX);
    float*  h0s  = smem + OFF_H0;
    float*  h1s  = smem + OFF_H1;
    float2* pA   = (float2*)(smem + OFF_PA);
    float2* pB   = (float2*)(smem + OFF_PB);
    float*  y0   = smem + OFF_Y0;
    float*  y1   = smem + OFF_Y1;
    float2* sbias= (float2*)(smem + OFF_BIA);
    float4* gc1  = (float4*)(smem + OFF_GC);
    float2* gcw  = (float2*)(smem + OFF_GW);

    const int tid  = threadIdx.x;
    const int grp  = tid >> 8;            // 0: k=0..75,  1: k=76..151
    const int lt   = tid & (NGRP - 1);
    const int b0   = blockIdx.x * 2;
    const int kb   = grp * KH;
    const bool mainw = (lt < 224);
    const int r0   = lt;
    const int ly   = lt - 224;

    const ulonglong2* wbase = (const ulonglong2*)sW4 + (size_t)grp * NSM * NMROW + r0;
    const ulonglong2* q0b   = (const ulonglong2*)h0s + grp * (KH / 4);
    const ulonglong2* q1b   = (const ulonglong2*)h1s + grp * (KH / 4);

    // ---------------- init ----------------
    u64 w0[KRH / 2], w1[KRH / 2];
    float m448[4], m449[4];

    if (mainw) {
        const float* wr0 = Whh + r0 * HID + kb;
        const float* wr1 = Whh + (r0 + 224) * HID + kb;
        #pragma unroll
        for (int p = 0; p < KRH / 2; p++) {       // k = kb..kb+43 < 150 always
            w0[p] = pack2(wr0[2 * p], wr0[2 * p + 1]);
            w1[p] = pack2(wr1[2 * p], wr1[2 * p + 1]);
        }
        #pragma unroll
        for (int gs = 0; gs < NSM; gs++) {        // k = kb+44 .. kb+75 (pad>=150)
            int k = KRH + 4 * gs;
            float4 v0, v1;
            v0.x = (kb + k + 0 < HID) ? wr0[k + 0] : 0.0f;
            v0.y = (kb + k + 1 < HID) ? wr0[k + 1] : 0.0f;
            v0.z = (kb + k + 2 < HID) ? wr0[k + 2] : 0.0f;
            v0.w = (kb + k + 3 < HID) ? wr0[k + 3] : 0.0f;
            v1.x = (kb + k + 0 < HID) ? wr1[k + 0] : 0.0f;
            v1.y = (kb + k + 1 < HID) ? wr1[k + 1] : 0.0f;
            v1.z = (kb + k + 2 < HID) ? wr1[k + 2] : 0.0f;
            v1.w = (kb + k + 3 < HID) ? wr1[k + 3] : 0.0f;
            sW4[(grp * NSM + gs) * NMROW + r0]       = v0;
            sW4[(grp * NSM + gs) * NMROW + r0 + 224] = v1;
        }
    } else {
        #pragma unroll
        for (int j = 0; j < 4; j++) {
            int k = kb + 4 * ly + j;               // valid work ly<19
            bool ok = (ly < 19) && (k < HID);
            m448[j] = ok ? Whh[448 * HID + k] : 0.0f;
            m449[j] = ok ? Whh[449 * HID + k] : 0.0f;
        }
    }

    // SMEM constant tables (replaces per-thread registers)
    for (int i = tid; i < 450; i += NTH) {
        float wv = (i < 2 * HID) ? Wih[i] : 0.0f;
        float bv = (i < 2 * HID) ? (bih[i] + bhh[i]) : bhh[i];
        sbias[i] = make_float2(wv, bv);
    }
    for (int i = tid; i < 75; i += NTH) {
        gc1[i] = make_float4(Wih[2 * HID + 2 * i],     bih[2 * HID + 2 * i],
                             Wih[2 * HID + 2 * i + 1], bih[2 * HID + 2 * i + 1]);
        gcw[i] = make_float2(Wlin[2 * i], Wlin[2 * i + 1]);
    }
    if (tid == 0) smem[OFF_BL] = blin[0];

    // Stage x (packed per-t), zero h (incl. pads)
    {
        const float* xr0 = x + (size_t)b0 * TLEN;
        const float* xr1 = x + (size_t)(b0 + 1) * TLEN;
        for (int i = tid; i < TLEN; i += NTH) sxp[i] = make_float2(xr0[i], xr1[i]);
        for (int i = tid; i < 160;  i += NTH) { h0s[i] = 0.0f; h1s[i] = 0.0f; }
    }
    __syncthreads();

    const bool gwarp = (lt < 96);          // warps 0-2 host the gate threads

    // ---------------- time loop ----------------
    for (int t = 0; t < TLEN; t++) {
        const float2 xt = sxp[t];

        if (mainw) {
            u64 a00 = 0, a01 = 0, a10 = 0, a11 = 0;   // a[row][batch]
            // Fused schedule: 8 iterations pair one smem k-group with one reg
            // k-group; 3 trailing reg-only groups.
            #pragma unroll
            for (int g = 0; g < NSM; g++) {
                const ulonglong2 wv0 = wbase[g * NMROW];
                const ulonglong2 wv1 = wbase[g * NMROW + 224];
                const ulonglong2 qr0 = q0b[g];
                const ulonglong2 qr1 = q1b[g];
                FFMA2(a00, w0[2 * g],     qr0.x);
                FFMA2(a01, w0[2 * g],     qr1.x);
                FFMA2(a10, w1[2 * g],     qr0.x);
                FFMA2(a11, w1[2 * g],     qr1.x);
                FFMA2(a00, w0[2 * g + 1], qr0.y);
                FFMA2(a01, w0[2 * g + 1], qr1.y);
                FFMA2(a10, w1[2 * g + 1], qr0.y);
                FFMA2(a11, w1[2 * g + 1], qr1.y);
                const ulonglong2 qs0 = q0b[NGR + g];
                const ulonglong2 qs1 = q1b[NGR + g];
                FFMA2(a00, wv0.x, qs0.x);
                FFMA2(a01, wv0.x, qs1.x);
                FFMA2(a10, wv1.x, qs0.x);
                FFMA2(a11, wv1.x, qs1.x);
                FFMA2(a00, wv0.y, qs0.y);
                FFMA2(a01, wv0.y, qs1.y);
                FFMA2(a10, wv1.y, qs0.y);
                FFMA2(a11, wv1.y, qs1.y);
            }
            #pragma unroll
            for (int g = NSM; g < NGR; g++) {          // reg-only groups 8,9,10
                const ulonglong2 qr0 = q0b[g];
                const ulonglong2 qr1 = q1b[g];
                FFMA2(a00, w0[2 * g],     qr0.x);
                FFMA2(a01, w0[2 * g],     qr1.x);
                FFMA2(a10, w1[2 * g],     qr0.x);
                FFMA2(a11, w1[2 * g],     qr1.x);
                FFMA2(a00, w0[2 * g + 1], qr0.y);
                FFMA2(a01, w0[2 * g + 1], qr1.y);
                FFMA2(a10, w1[2 * g + 1], qr0.y);
                FFMA2(a11, w1[2 * g + 1], qr1.y);
            }
            if (grp == 0) {
                const float2 bb0 = sbias[r0];
                const float2 bb1 = sbias[r0 + 224];
                pA[r0]       = make_float2(rsum2(a00) + fmaf(xt.x, bb0.x, bb0.y),
                                           rsum2(a01) + fmaf(xt.y, bb0.x, bb0.y));
                pA[r0 + 224] = make_float2(rsum2(a10) + fmaf(xt.x, bb1.x, bb1.y),
                                           rsum2(a11) + fmaf(xt.y, bb1.x, bb1.y));
            } else {
                pB[r0]       = make_float2(rsum2(a00), rsum2(a01));
                pB[r0 + 224] = make_float2(rsum2(a10), rsum2(a11));
            }
        } else {
            // warp 7: rows 448,449 k-distributed over 19 lanes (4 k's each)
            float s0a = 0.f, s0b = 0.f, s1a = 0.f, s1b = 0.f;
            if (ly < 19) {
                const float4 q0 = ((const float4*)h0s)[(kb >> 2) + ly];
                const float4 q1 = ((const float4*)h1s)[(kb >> 2) + ly];
                s0a = fmaf(m448[0], q0.x, fmaf(m448[1], q0.y, fmaf(m448[2], q0.z, m448[3] * q0.w)));
                s0b = fmaf(m448[0], q1.x, fmaf(m448[1], q1.y, fmaf(m448[2], q1.z, m448[3] * q1.w)));
                s1a = fmaf(m449[0], q0.x, fmaf(m449[1], q0.y, fmaf(m449[2], q0.z, m449[3] * q0.w)));
                s1b = fmaf(m449[0], q1.x, fmaf(m449[1], q1.y, fmaf(m449[2], q1.z, m449[3] * q1.w)));
            }
            #pragma unroll
            for (int d = 16; d > 0; d >>= 1) {
                s0a += __shfl_xor_sync(0xffffffffu, s0a, d);
                s0b += __shfl_xor_sync(0xffffffffu, s0b, d);
                s1a += __shfl_xor_sync(0xffffffffu, s1a, d);
                s1b += __shfl_xor_sync(0xffffffffu, s1b, d);
            }
            if (ly == 0) {
                const float2 sb = make_float2(sbias[448].y, sbias[449].y);
                if (grp == 0) {
                    pA[448] = make_float2(s0a + sb.x, s0b + sb.x);
                    pA[449] = make_float2(s1a + sb.y, s1b + sb.y);
                } else {
                    pB[448] = make_float2(s0a, s0b);
                    pB[449] = make_float2(s1a, s1b);
                }
            }
        }

        // barrier 1: pA/pB ready. Only gate-hosting warps need to wait.
        if (gwarp) {
            BAR_SYNC(1);
            // gate: thread u<75 of group g updates units 2u,2u+1 for batch g
            if (lt < 75) {
                const int u = lt;
                const float xb = grp ? xt.y : xt.x;
                float* hs = grp ? h1s : h0s;
                float* yb = grp ? y1  : y0;

                const float4 va = ((const float4*)pA)[u];
                const float4 vb = ((const float4*)pB)[u];
                const float4 za = ((const float4*)(pA + HID))[u];
                const float4 zb = ((const float4*)(pB + HID))[u];
                const float4 na = ((const float4*)(pA + 2 * HID))[u];
                const float4 nb = ((const float4*)(pB + 2 * HID))[u];

                const float gr0 = grp ? (va.y + vb.y) : (va.x + vb.x);
                const float gr1 = grp ? (va.w + vb.w) : (va.z + vb.z);
                const float gz0 = grp ? (za.y + zb.y) : (za.x + zb.x);
                const float gz1 = grp ? (za.w + zb.w) : (za.z + zb.z);
                const float gn0 = grp ? (na.y + nb.y) : (na.x + nb.x);
                const float gn1 = grp ? (na.w + nb.w) : (na.z + nb.z);

                const float2 h  = ((const float2*)hs)[u];
                const float4 gc = gc1[u];
                const float2 gw = gcw[u];

                const float in0 = fmaf(xb, gc.x, gc.y);
                const float in1 = fmaf(xb, gc.z, gc.w);
                const float r0g = sigt(gr0);
                const float r1g = sigt(gr1);
                const float z0g = sigt(gz0);
                const float z1g = sigt(gz1);
                const float n0g = tanha(fmaf(r0g, gn0, in0));
                const float n1g = tanha(fmaf(r1g, gn1, in1));
                const float hn0 = fmaxf(0.0f, fmaf(z0g, h.x - n0g, n0g));
                const float hn1 = fmaxf(0.0f, fmaf(z1g, h.y - n1g, n1g));

                ((float2*)hs)[u] = make_float2(hn0, hn1);
                ((float2*)yb)[u] = make_float2(hn0 * gw.x, hn1 * gw.y);
            }
        } else {
            BAR_ARRIVE(1);
        }

        BAR_SYNC(2);   // h + y ready

        // y head: warp 7 of each group reduces its batch (overlaps next matvec)
        if (!mainw) {
            const float* yb = grp ? y1 : y0;
            float s = yb[ly] + yb[ly + 32] + yb[ly + 64] + yb[ly + 96]
                    + ((ly + 128 < HID) ? yb[ly + 128] : 0.0f);
            s += __shfl_xor_sync(0xffffffffu, s, 16);
            s += __shfl_xor_sync(0xffffffffu, s, 8);
            s += __shfl_xor_sync(0xffffffffu, s, 4);
            s += __shfl_xor_sync(0xffffffffu, s, 2);
            s += __shfl_xor_sync(0xffffffffu, s, 1);
            if (ly == 0) {
                out[(size_t)(b0 + grp) * TLEN + t] = s + smem[OFF_BL];
            }
        }
    }
}

extern "C" void kernel_launch(void* const* d_in, const int* in_sizes, int n_in,
                              void* d_out, int out_size) {
    const float* x    = (const float*)d_in[0];
    const float* Wih  = (const float*)d_in[1];
    const float* Whh  = (const float*)d_in[2];
    const float* bih  = (const float*)d_in[3];
    const float* bhh  = (const float*)d_in[4];
    const float* Wlin = (const float*)d_in[5];
    const float* blin = (const float*)d_in[6];
    float* out = (float*)d_out;

    const size_t smem_bytes = SMEM_FLOATS * sizeof(float);   // 146,320 B
    cudaFuncSetAttribute(gru_persistent,
                         cudaFuncAttributeMaxDynamicSharedMemorySize,
                         (int)smem_bytes);

    gru_persistent<<<128, NTH, smem_bytes>>>(x, Wih, Whh, bih, bhh, Wlin, blin, out);
}

// round 15
// speedup vs baseline: 1.0544x; 1.0544x over previous
#include <cuda_runtime.h>
#include <math.h>

// GRU recurrence, persistent kernel, round 14: R8 structure + KRH=44 only.
// B=256, T=2048, H=150 (3H=450 gate rows), I=O=1.
// 128 CTAs x 512 threads; CTA owns batches (2*cta, 2*cta+1).
// Two K-half groups of 256 threads: grp 0 k=0..75, grp 1 k=76..151.
// Warps 0-6 per group (lt<224): rows lt, lt+224. Warp 7: rows 448/449 + y-head.
// Per main thread: 44 W floats/row in regs (f32x2 pairs), 32/row in SMEM.
// Gate: threads lt<150 per group, 1 hidden unit each (R8 layout).
// Row bias/input-weight and gate constants live in SMEM tables (register diet).

#define NTH     512
#define NGRP    256
#define HID     150
#define TLEN    2048
#define KH      76         // K per half (152 padded)
#define KRH     44         // reg W floats per half-row (22 u64)
#define NGR     11         // 4-float reg k-groups
#define NSM     8          // 4-float smem k-groups (32 floats)
#define NMROW   448

// SMEM layout (floats):
#define OFF_SW   0                          // float4 [16][448] = 28672
#define OFF_SX   28672                      // float2[2048] = 4096
#define OFF_H0   32768                      // 160
#define OFF_H1   32928                      // 160
#define OFF_PA   33088                      // float2[452] = 904
#define OFF_PB   33992                      // float2[452] = 904
#define OFF_Y0   34896                      // 160
#define OFF_Y1   35056                      // 160
#define OFF_BIA  35216                      // float2[452]: (wih, bias) per row
#define OFF_GCT  36120                      // float4[150]: (win, bin, wlin, 0)
#define OFF_BL   36720                      // 1
#define SMEM_FLOATS 36724                   // 146,896 B

typedef unsigned long long u64;

#define FFMA2(d, a, b) asm("fma.rn.f32x2 %0, %1, %2, %0;" : "+l"(d) : "l"(a), "l"(b))

__device__ __forceinline__ u64 pack2(float a, float b) {
    u64 r; asm("mov.b64 %0, {%1, %2};" : "=l"(r) : "f"(a), "f"(b)); return r;
}
__device__ __forceinline__ float rsum2(u64 v) {
    float lo, hi; asm("mov.b64 {%0, %1}, %2;" : "=f"(lo), "=f"(hi) : "l"(v));
    return lo + hi;
}
__device__ __forceinline__ float tanha(float x) {       // MUFU.TANH
    float y; asm("tanh.approx.f32 %0, %1;" : "=f"(y) : "f"(x)); return y;
}
__device__ __forceinline__ float sigt(float v) {        // sigmoid via tanh.approx
    return fmaf(0.5f, tanha(0.5f * v), 0.5f);
}

extern "C" __global__ void __launch_bounds__(NTH, 1)
gru_persistent(const float* __restrict__ x,     // [B][T]
               const float* __restrict__ Wih,   // [450][1]
               const float* __restrict__ Whh,   // [450][150]
               const float* __restrict__ bih,   // [450]
               const float* __restrict__ bhh,   // [450]
               const float* __restrict__ Wlin,  // [1][150]
               const float* __restrict__ blin,  // [1]
               float* __restrict__ out)         // [B][T]
{
    extern __shared__ float smem[];
    float4* sW4  = (float4*)(smem + OFF_SW);
    float2* sxp  = (float2*)(smem + OFF_SX);
    float*  h0s  = smem + OFF_H0;
    float*  h1s  = smem + OFF_H1;
    float2* pA   = (float2*)(smem + OFF_PA);
    float2* pB   = (float2*)(smem + OFF_PB);
    float*  y0   = smem + OFF_Y0;
    float*  y1   = smem + OFF_Y1;
    float2* sbias= (float2*)(smem + OFF_BIA);
    float4* gct  = (float4*)(smem + OFF_GCT);

    const int tid  = threadIdx.x;
    const int grp  = tid >> 8;            // 0: k=0..75,  1: k=76..151
    const int lt   = tid & (NGRP - 1);
    const int b0   = blockIdx.x * 2;
    const int kb   = grp * KH;
    const bool mainw = (lt < 224);
    const int r0   = lt;
    const int ly   = lt - 224;

    const ulonglong2* wbase = (const ulonglong2*)sW4 + (size_t)grp * NSM * NMROW + r0;
    const ulonglong2* q0b   = (const ulonglong2*)h0s + grp * (KH / 4);
    const ulonglong2* q1b   = (const ulonglong2*)h1s + grp * (KH / 4);

    // ---------------- init ----------------
    u64 w0[KRH / 2], w1[KRH / 2];
    float m448[4], m449[4];

    if (mainw) {
        const float* wr0 = Whh + r0 * HID + kb;
        const float* wr1 = Whh + (r0 + 224) * HID + kb;
        #pragma unroll
        for (int p = 0; p < KRH / 2; p++) {       // k = kb..kb+43 < 150 always
            w0[p] = pack2(wr0[2 * p], wr0[2 * p + 1]);
            w1[p] = pack2(wr1[2 * p], wr1[2 * p + 1]);
        }
        #pragma unroll
        for (int gs = 0; gs < NSM; gs++) {        // k = kb+44 .. kb+75 (pad>=150)
            int k = KRH + 4 * gs;
            float4 v0, v1;
            v0.x = (kb + k + 0 < HID) ? wr0[k + 0] : 0.0f;
            v0.y = (kb + k + 1 < HID) ? wr0[k + 1] : 0.0f;
            v0.z = (kb + k + 2 < HID) ? wr0[k + 2] : 0.0f;
            v0.w = (kb + k + 3 < HID) ? wr0[k + 3] : 0.0f;
            v1.x = (kb + k + 0 < HID) ? wr1[k + 0] : 0.0f;
            v1.y = (kb + k + 1 < HID) ? wr1[k + 1] : 0.0f;
            v1.z = (kb + k + 2 < HID) ? wr1[k + 2] : 0.0f;
            v1.w = (kb + k + 3 < HID) ? wr1[k + 3] : 0.0f;
            sW4[(grp * NSM + gs) * NMROW + r0]       = v0;
            sW4[(grp * NSM + gs) * NMROW + r0 + 224] = v1;
        }
    } else {
        #pragma unroll
        for (int j = 0; j < 4; j++) {
            int k = kb + 4 * ly + j;               // valid work ly<19
            bool ok = (ly < 19) && (k < HID);
            m448[j] = ok ? Whh[448 * HID + k] : 0.0f;
            m449[j] = ok ? Whh[449 * HID + k] : 0.0f;
        }
    }

    // SMEM constant tables (register diet: frees wih/bias/win/bin/wlin regs)
    for (int i = tid; i < 450; i += NTH) {
        float wv = (i < 2 * HID) ? Wih[i] : 0.0f;
        float bv = (i < 2 * HID) ? (bih[i] + bhh[i]) : bhh[i];
        sbias[i] = make_float2(wv, bv);
    }
    for (int i = tid; i < HID; i += NTH) {
        gct[i] = make_float4(Wih[2 * HID + i], bih[2 * HID + i], Wlin[i], 0.0f);
    }
    if (tid == 0) smem[OFF_BL] = blin[0];

    // Stage x (packed per-t), zero h (incl. pads)
    {
        const float* xr0 = x + (size_t)b0 * TLEN;
        const float* xr1 = x + (size_t)(b0 + 1) * TLEN;
        for (int i = tid; i < TLEN; i += NTH) sxp[i] = make_float2(xr0[i], xr1[i]);
        for (int i = tid; i < 160;  i += NTH) { h0s[i] = 0.0f; h1s[i] = 0.0f; }
    }
    __syncthreads();

    // ---------------- time loop ----------------
    for (int t = 0; t < TLEN; t++) {
        const float2 xt = sxp[t];

        if (mainw) {
            u64 a00 = 0, a01 = 0, a10 = 0, a11 = 0;   // a[row][batch]
            // Fused schedule: 8 iterations pair one smem k-group with one reg
            // k-group; 3 trailing reg-only groups.
            #pragma unroll
            for (int g = 0; g < NSM; g++) {
                const ulonglong2 wv0 = wbase[g * NMROW];
                const ulonglong2 wv1 = wbase[g * NMROW + 224];
                const ulonglong2 qr0 = q0b[g];
                const ulonglong2 qr1 = q1b[g];
                FFMA2(a00, w0[2 * g],     qr0.x);
                FFMA2(a01, w0[2 * g],     qr1.x);
                FFMA2(a10, w1[2 * g],     qr0.x);
                FFMA2(a11, w1[2 * g],     qr1.x);
                FFMA2(a00, w0[2 * g + 1], qr0.y);
                FFMA2(a01, w0[2 * g + 1], qr1.y);
                FFMA2(a10, w1[2 * g + 1], qr0.y);
                FFMA2(a11, w1[2 * g + 1], qr1.y);
                const ulonglong2 qs0 = q0b[NGR + g];
                const ulonglong2 qs1 = q1b[NGR + g];
                FFMA2(a00, wv0.x, qs0.x);
                FFMA2(a01, wv0.x, qs1.x);
                FFMA2(a10, wv1.x, qs0.x);
                FFMA2(a11, wv1.x, qs1.x);
                FFMA2(a00, wv0.y, qs0.y);
                FFMA2(a01, wv0.y, qs1.y);
                FFMA2(a10, wv1.y, qs0.y);
                FFMA2(a11, wv1.y, qs1.y);
            }
            #pragma unroll
            for (int g = NSM; g < NGR; g++) {          // reg-only groups 8,9,10
                const ulonglong2 qr0 = q0b[g];
                const ulonglong2 qr1 = q1b[g];
                FFMA2(a00, w0[2 * g],     qr0.x);
                FFMA2(a01, w0[2 * g],     qr1.x);
                FFMA2(a10, w1[2 * g],     qr0.x);
                FFMA2(a11, w1[2 * g],     qr1.x);
                FFMA2(a00, w0[2 * g + 1], qr0.y);
                FFMA2(a01, w0[2 * g + 1], qr1.y);
                FFMA2(a10, w1[2 * g + 1], qr0.y);
                FFMA2(a11, w1[2 * g + 1], qr1.y);
            }
            if (grp == 0) {
                const float2 bb0 = sbias[r0];
                const float2 bb1 = sbias[r0 + 224];
                pA[r0]       = make_float2(rsum2(a00) + fmaf(xt.x, bb0.x, bb0.y),
                                           rsum2(a01) + fmaf(xt.y, bb0.x, bb0.y));
                pA[r0 + 224] = make_float2(rsum2(a10) + fmaf(xt.x, bb1.x, bb1.y),
                                           rsum2(a11) + fmaf(xt.y, bb1.x, bb1.y));
            } else {
                pB[r0]       = make_float2(rsum2(a00), rsum2(a01));
                pB[r0 + 224] = make_float2(rsum2(a10), rsum2(a11));
            }
        } else {
            // warp 7: rows 448,449 k-distributed over 19 lanes (4 k's each)
            float s0a = 0.f, s0b = 0.f, s1a = 0.f, s1b = 0.f;
            if (ly < 19) {
                const float4 q0 = ((const float4*)h0s)[(kb >> 2) + ly];
                const float4 q1 = ((const float4*)h1s)[(kb >> 2) + ly];
                s0a = fmaf(m448[0], q0.x, fmaf(m448[1], q0.y, fmaf(m448[2], q0.z, m448[3] * q0.w)));
                s0b = fmaf(m448[0], q1.x, fmaf(m448[1], q1.y, fmaf(m448[2], q1.z, m448[3] * q1.w)));
                s1a = fmaf(m449[0], q0.x, fmaf(m449[1], q0.y, fmaf(m449[2], q0.z, m449[3] * q0.w)));
                s1b = fmaf(m449[0], q1.x, fmaf(m449[1], q1.y, fmaf(m449[2], q1.z, m449[3] * q1.w)));
            }
            #pragma unroll
            for (int d = 16; d > 0; d >>= 1) {
                s0a += __shfl_xor_sync(0xffffffffu, s0a, d);
                s0b += __shfl_xor_sync(0xffffffffu, s0b, d);
                s1a += __shfl_xor_sync(0xffffffffu, s1a, d);
                s1b += __shfl_xor_sync(0xffffffffu, s1b, d);
            }
            if (ly == 0) {
                const float bA = sbias[448].y;
                const float bBv = sbias[449].y;
                if (grp == 0) {
                    pA[448] = make_float2(s0a + bA, s0b + bA);
                    pA[449] = make_float2(s1a + bBv, s1b + bBv);
                } else {
                    pB[448] = make_float2(s0a, s0b);
                    pB[449] = make_float2(s1a, s1b);
                }
            }
        }
        __syncthreads();

        // gate stage: group g's threads lt<150 handle batch g, unit lt (R8 form)
        if (lt < HID) {
            const float xb = grp ? xt.y : xt.x;
            float*      hs = grp ? h1s : h0s;
            float*      yb = grp ? y1  : y0;

            const float2 vr  = pA[lt];
            const float2 wr_ = pB[lt];
            const float2 vz  = pA[lt + HID];
            const float2 wz  = pB[lt + HID];
            const float2 vn  = pA[lt + 2 * HID];
            const float2 wn  = pB[lt + 2 * HID];
            const float4 gc  = gct[lt];

            const float gr = grp ? (vr.y + wr_.y) : (vr.x + wr_.x);
            const float gz = grp ? (vz.y + wz.y) : (vz.x + wz.x);
            const float gn = grp ? (vn.y + wn.y) : (vn.x + wn.x);
            const float h  = hs[lt];

            const float in = fmaf(xb, gc.x, gc.y);
            const float r  = sigt(gr);
            const float z  = sigt(gz);
            const float n  = tanha(fmaf(r, gn, in));
            const float hn = fmaxf(0.0f, fmaf(z, h - n, n));

            hs[lt] = hn;
            yb[lt] = hn * gc.z;
        }
        __syncthreads();

        // y head: warp 7 of each group reduces its batch (overlaps next matvec)
        if (!mainw) {
            const float* yb = grp ? y1 : y0;
            float s = yb[ly] + yb[ly + 32] + yb[ly + 64] + yb[ly + 96]
                    + ((ly + 128 < HID) ? yb[ly + 128] : 0.0f);
            s += __shfl_xor_sync(0xffffffffu, s, 16);
            s += __shfl_xor_sync(0xffffffffu, s, 8);
            s += __shfl_xor_sync(0xffffffffu, s, 4);
            s += __shfl_xor_sync(0xffffffffu, s, 2);
            s += __shfl_xor_sync(0xffffffffu, s, 1);
            if (ly == 0) {
                out[(size_t)(b0 + grp) * TLEN + t] = s + smem[OFF_BL];
            }
        }
    }
}

extern "C" void kernel_launch(void* const* d_in, const int* in_sizes, int n_in,
                              void* d_out, int out_size) {
    const float* x    = (const float*)d_in[0];
    const float* Wih  = (const float*)d_in[1];
    const float* Whh  = (const float*)d_in[2];
    const float* bih  = (const float*)d_in[3];
    const float* bhh  = (const float*)d_in[4];
    const float* Wlin = (const float*)d_in[5];
    const float* blin = (const float*)d_in[6];
    float* out = (float*)d_out;

    const size_t smem_bytes = SMEM_FLOATS * sizeof(float);   // 146,896 B
    cudaFuncSetAttribute(gru_persistent,
                         cudaFuncAttributeMaxDynamicSharedMemorySize,
                         (int)smem_bytes);

    gru_persistent<<<128, NTH, smem_bytes>>>(x, Wih, Whh, bih, bhh, Wlin, blin, out);
}

// round 17
// speedup vs baseline: 1.0557x; 1.0013x over previous
#include <cuda_runtime.h>
#include <math.h>

// GRU recurrence, persistent kernel, round 15: R8 base + W-preload into dead
// accumulator registers (relocates 2 LDS.128/warp/step into the gate bubble).
// B=256, T=2048, H=150 (3H=450 gate rows), I=O=1.
// 128 CTAs x 512 threads; CTA owns batches (2*cta, 2*cta+1).
// Two K-half groups of 256 threads: grp 0 k=0..75, grp 1 k=76..151.
// Warps 0-6 per group (lt<224): rows lt, lt+224. Warp 7: rows 448/449 + y-head.
// Per main thread: 40 W floats/row in regs (f32x2 pairs), 36/row in SMEM.

#define NTH     512
#define NGRP    256
#define HID     150
#define G2      300
#define TLEN    2048
#define KH      76         // K per half (152 padded)
#define KRH     40         // reg W floats per half-row (20 u64)
#define NGR     10         // 4-float reg k-groups
#define NSM     9          // 4-float smem k-groups (36 floats)
#define NMROW   448        // rows covered by main warps

// SMEM layout (floats):
#define OFF_SW   0                          // float4 [2*NSM][448] = 32256 floats
#define OFF_SX   (2*NSM*NMROW*4)            // float2[2048] = 4096
#define OFF_H0   (OFF_SX + 2*TLEN)          // 160
#define OFF_H1   (OFF_H0 + 160)             // 160
#define OFF_PA   (OFF_H1 + 160)             // float2[452] = 904
#define OFF_PB   (OFF_PA + 904)             // float2[452] = 904
#define OFF_Y0   (OFF_PB + 904)             // 160
#define OFF_Y1   (OFF_Y0 + 160)             // 160
#define SMEM_FLOATS (OFF_Y1 + 160)          // 38800 floats = 155,200 B

typedef unsigned long long u64;

#define FFMA2(d, a, b) asm("fma.rn.f32x2 %0, %1, %2, %0;" : "+l"(d) : "l"(a), "l"(b))

__device__ __forceinline__ u64 mul2(u64 a, u64 b) {
    u64 r; asm("mul.rn.f32x2 %0, %1, %2;" : "=l"(r) : "l"(a), "l"(b)); return r;
}
__device__ __forceinline__ u64 pack2(float a, float b) {
    u64 r; asm("mov.b64 %0, {%1, %2};" : "=l"(r) : "f"(a), "f"(b)); return r;
}
__device__ __forceinline__ float rsum2(u64 v) {
    float lo, hi; asm("mov.b64 {%0, %1}, %2;" : "=f"(lo), "=f"(hi) : "l"(v));
    return lo + hi;
}
__device__ __forceinline__ float tanha(float x) {       // MUFU.TANH
    float y; asm("tanh.approx.f32 %0, %1;" : "=f"(y) : "f"(x)); return y;
}
__device__ __forceinline__ float sigt(float v) {        // sigmoid via tanh.approx
    return fmaf(0.5f, tanha(0.5f * v), 0.5f);
}

extern "C" __global__ void __launch_bounds__(NTH, 1)
gru_persistent(const float* __restrict__ x,     // [B][T]
               const float* __restrict__ Wih,   // [450][1]
               const float* __restrict__ Whh,   // [450][150]
               const float* __restrict__ bih,   // [450]
               const float* __restrict__ bhh,   // [450]
               const float* __restrict__ Wlin,  // [1][150]
               const float* __restrict__ blin,  // [1]
               float* __restrict__ out)         // [B][T]
{
    extern __shared__ float smem[];
    float4* sW4 = (float4*)(smem + OFF_SW);     // [(grp*NSM+gs)*448 + row]
    float2* sxp = (float2*)(smem + OFF_SX);     // (x_b0, x_b1) per t
    float*  h0s = smem + OFF_H0;
    float*  h1s = smem + OFF_H1;
    float2* pA  = (float2*)(smem + OFF_PA);     // group A partial, (b0,b1)/row
    float2* pB  = (float2*)(smem + OFF_PB);
    float*  y0  = smem + OFF_Y0;
    float*  y1  = smem + OFF_Y1;

    const int tid  = threadIdx.x;
    const int grp  = tid >> 8;            // 0: k=0..75,  1: k=76..151
    const int lt   = tid & (NGRP - 1);
    const int b0   = blockIdx.x * 2;
    const int kb   = grp * KH;
    const bool mainw = (lt < 224);
    const int r0   = lt;
    const int ly   = lt - 224;

    // Base pointers folded per-thread so loop LDS use [reg + imm] only.
    const ulonglong2* wbase = (const ulonglong2*)sW4 + (size_t)grp * NSM * NMROW + r0;
    const ulonglong2* q0b   = (const ulonglong2*)h0s + grp * (KH / 4);
    const ulonglong2* q1b   = (const ulonglong2*)h1s + grp * (KH / 4);

    // ---------------- init ----------------
    u64 w0[KRH / 2], w1[KRH / 2];         // main-thread reg W (packed k-pairs)
    float m448[4], m449[4];               // warp-7 mini W
    float b448 = 0.0f, b449 = 0.0f;

    if (mainw) {
        const float* wr0 = Whh + r0 * HID + kb;
        const float* wr1 = Whh + (r0 + 224) * HID + kb;
        #pragma unroll
        for (int p = 0; p < KRH / 2; p++) {       // k = kb..kb+39 < 150 always
            w0[p] = pack2(wr0[2 * p], wr0[2 * p + 1]);
            w1[p] = pack2(wr1[2 * p], wr1[2 * p + 1]);
        }
        #pragma unroll
        for (int gs = 0; gs < NSM; gs++) {        // k = kb+40 .. kb+75 (pad>=150)
            int k = KRH + 4 * gs;
            float4 v0, v1;
            v0.x = (kb + k + 0 < HID) ? wr0[k + 0] : 0.0f;
            v0.y = (kb + k + 1 < HID) ? wr0[k + 1] : 0.0f;
            v0.z = (kb + k + 2 < HID) ? wr0[k + 2] : 0.0f;
            v0.w = (kb + k + 3 < HID) ? wr0[k + 3] : 0.0f;
            v1.x = (kb + k + 0 < HID) ? wr1[k + 0] : 0.0f;
            v1.y = (kb + k + 1 < HID) ? wr1[k + 1] : 0.0f;
            v1.z = (kb + k + 2 < HID) ? wr1[k + 2] : 0.0f;
            v1.w = (kb + k + 3 < HID) ? wr1[k + 3] : 0.0f;
            sW4[(grp * NSM + gs) * NMROW + r0]       = v0;
            sW4[(grp * NSM + gs) * NMROW + r0 + 224] = v1;
        }
    } else {
        #pragma unroll
        for (int j = 0; j < 4; j++) {
            int k = kb + 4 * ly + j;               // valid work ly<19
            bool ok = (ly < 19) && (k < HID);
            m448[j] = ok ? Whh[448 * HID + k] : 0.0f;
            m449[j] = ok ? Whh[449 * HID + k] : 0.0f;
        }
        b448 = bhh[448];
        b449 = bhh[449];
    }

    // Per-row input weight / bias (added by group A only).
    float wih0 = 0.0f, bias0 = 0.0f, wih1 = 0.0f, bias1 = 0.0f;
    if (grp == 0 && mainw) {
        const int r1 = r0 + 224;
        wih0  = (r0 < G2) ? Wih[r0] : 0.0f;
        bias0 = (r0 < G2) ? (bih[r0] + bhh[r0]) : bhh[r0];
        wih1  = (r1 < G2) ? Wih[r1] : 0.0f;
        bias1 = (r1 < G2) ? (bih[r1] + bhh[r1]) : bhh[r1];
    }

    // Gate-stage constants (lt < 150; group g handles batch g)
    float win = 0.0f, bin = 0.0f, wlin = 0.0f;
    if (lt < HID) {
        win  = Wih[2 * HID + lt];
        bin  = bih[2 * HID + lt];
        wlin = Wlin[lt];
    }
    const float bl = __ldg(blin);

    // Stage x (packed per-t), zero h (incl. pads)
    {
        const float* xr0 = x + (size_t)b0 * TLEN;
        const float* xr1 = x + (size_t)(b0 + 1) * TLEN;
        for (int i = tid; i < TLEN; i += NTH) sxp[i] = make_float2(xr0[i], xr1[i]);
        for (int i = tid; i < 160;  i += NTH) { h0s[i] = 0.0f; h1s[i] = 0.0f; }
    }
    __syncthreads();

    float* or0 = out + (size_t)b0 * TLEN;
    float* or1 = out + (size_t)(b0 + 1) * TLEN;

    // Accumulators double as the W-preload registers between steps.
    u64 a00 = 0, a01 = 0, a10 = 0, a11 = 0;
    if (mainw) {   // prologue preload of smem-iteration 0's W pair
        const ulonglong2 p0 = wbase[0];
        const ulonglong2 p1 = wbase[224];
        a00 = p0.x; a01 = p0.y;
        a10 = p1.x; a11 = p1.y;
    }

    // ---------------- time loop ----------------
    for (int t = 0; t < TLEN; t++) {
        const float2 xt = sxp[t];

        if (mainw) {
            // --- smem k-group 0: consume preloaded W held in the accumulators.
            // Entry: a00=wv0.x, a01=wv0.y, a10=wv1.x, a11=wv1.y.
            {
                const ulonglong2 qs0 = q0b[NGR];
                const ulonglong2 qs1 = q1b[NGR];
                u64 tq;
                tq  = a01;                    // save wv0.y
                a01 = mul2(a00, qs1.x);       // row0,b1 init (wv0.x)
                a00 = mul2(a00, qs0.x);       // row0,b0 init
                FFMA2(a00, tq, qs0.y);
                FFMA2(a01, tq, qs1.y);
                tq  = a11;                    // save wv1.y
                a11 = mul2(a10, qs1.x);       // row1,b1 init (wv1.x)
                a10 = mul2(a10, qs0.x);       // row1,b0 init
                FFMA2(a10, tq, qs0.y);
                FFMA2(a11, tq, qs1.y);
            }
            // --- iterations 1..8: load wv(g), reg-group g-1, smem-group g.
            #pragma unroll
            for (int g = 1; g < NSM; g++) {
                const ulonglong2 wv0 = wbase[g * NMROW];
                const ulonglong2 wv1 = wbase[g * NMROW + 224];
                const ulonglong2 qr0 = q0b[g - 1];
                const ulonglong2 qr1 = q1b[g - 1];
                FFMA2(a00, w0[2 * (g - 1)],     qr0.x);
                FFMA2(a01, w0[2 * (g - 1)],     qr1.x);
                FFMA2(a10, w1[2 * (g - 1)],     qr0.x);
                FFMA2(a11, w1[2 * (g - 1)],     qr1.x);
                FFMA2(a00, w0[2 * (g - 1) + 1], qr0.y);
                FFMA2(a01, w0[2 * (g - 1) + 1], qr1.y);
                FFMA2(a10, w1[2 * (g - 1) + 1], qr0.y);
                FFMA2(a11, w1[2 * (g - 1) + 1], qr1.y);
                const ulonglong2 qs0 = q0b[NGR + g];
                const ulonglong2 qs1 = q1b[NGR + g];
                FFMA2(a00, wv0.x, qs0.x);
                FFMA2(a01, wv0.x, qs1.x);
                FFMA2(a10, wv1.x, qs0.x);
                FFMA2(a11, wv1.x, qs1.x);
                FFMA2(a00, wv0.y, qs0.y);
                FFMA2(a01, wv0.y, qs1.y);
                FFMA2(a10, wv1.y, qs0.y);
                FFMA2(a11, wv1.y, qs1.y);
            }
            // --- trailing reg-only k-groups 8, 9.
            #pragma unroll
            for (int g = NSM - 1; g < NGR; g++) {
                const ulonglong2 qr0 = q0b[g];
                const ulonglong2 qr1 = q1b[g];
                FFMA2(a00, w0[2 * g],     qr0.x);
                FFMA2(a01, w0[2 * g],     qr1.x);
                FFMA2(a10, w1[2 * g],     qr0.x);
                FFMA2(a11, w1[2 * g],     qr1.x);
                FFMA2(a00, w0[2 * g + 1], qr0.y);
                FFMA2(a01, w0[2 * g + 1], qr1.y);
                FFMA2(a10, w1[2 * g + 1], qr0.y);
                FFMA2(a11, w1[2 * g + 1], qr1.y);
            }
            if (grp == 0) {
                pA[r0]       = make_float2(rsum2(a00) + fmaf(xt.x, wih0, bias0),
                                           rsum2(a01) + fmaf(xt.y, wih0, bias0));
                pA[r0 + 224] = make_float2(rsum2(a10) + fmaf(xt.x, wih1, bias1),
                                           rsum2(a11) + fmaf(xt.y, wih1, bias1));
            } else {
                pB[r0]       = make_float2(rsum2(a00), rsum2(a01));
                pB[r0 + 224] = make_float2(rsum2(a10), rsum2(a11));
            }
            // --- preload next step's smem-iteration-0 W into the (now dead)
            // accumulators; completes during the bar/gate bubble.
            {
                const ulonglong2 p0 = wbase[0];
                const ulonglong2 p1 = wbase[224];
                a00 = p0.x; a01 = p0.y;
                a10 = p1.x; a11 = p1.y;
            }
        } else {
            // warp 7: rows 448,449 k-distributed over 19 lanes (4 k's each)
            float s0a = 0.f, s0b = 0.f, s1a = 0.f, s1b = 0.f;
            if (ly < 19) {
                const float4 q0 = ((const float4*)h0s)[(kb >> 2) + ly];
                const float4 q1 = ((const float4*)h1s)[(kb >> 2) + ly];
                s0a = fmaf(m448[0], q0.x, fmaf(m448[1], q0.y, fmaf(m448[2], q0.z, m448[3] * q0.w)));
                s0b = fmaf(m448[0], q1.x, fmaf(m448[1], q1.y, fmaf(m448[2], q1.z, m448[3] * q1.w)));
                s1a = fmaf(m449[0], q0.x, fmaf(m449[1], q0.y, fmaf(m449[2], q0.z, m449[3] * q0.w)));
                s1b = fmaf(m449[0], q1.x, fmaf(m449[1], q1.y, fmaf(m449[2], q1.z, m449[3] * q1.w)));
            }
            #pragma unroll
            for (int d = 16; d > 0; d >>= 1) {
                s0a += __shfl_xor_sync(0xffffffffu, s0a, d);
                s0b += __shfl_xor_sync(0xffffffffu, s0b, d);
                s1a += __shfl_xor_sync(0xffffffffu, s1a, d);
                s1b += __shfl_xor_sync(0xffffffffu, s1b, d);
            }
            if (ly == 0) {
                if (grp == 0) {
                    pA[448] = make_float2(s0a + b448, s0b + b448);
                    pA[449] = make_float2(s1a + b449, s1b + b449);
                } else {
                    pB[448] = make_float2(s0a, s0b);
                    pB[449] = make_float2(s1a, s1b);
                }
            }
        }
        __syncthreads();

        // gate stage: group g's threads lt<150 handle batch g, unit lt
        if (lt < HID) {
            const float xb = grp ? xt.y : xt.x;
            float*      hs = grp ? h1s : h0s;
            float*      yb = grp ? y1  : y0;

            const float2 vr  = pA[lt];
            const float2 wr_ = pB[lt];
            const float2 vz  = pA[lt + HID];
            const float2 wz  = pB[lt + HID];
            const float2 vn  = pA[lt + 2 * HID];
            const float2 wn  = pB[lt + 2 * HID];

            const float gr = grp ? (vr.y + wr_.y) : (vr.x + wr_.x);
            const float gz = grp ? (vz.y + wz.y) : (vz.x + wz.x);
            const float gn = grp ? (vn.y + wn.y) : (vn.x + wn.x);
            const float h  = hs[lt];

            const float in = fmaf(xb, win, bin);
            const float r  = sigt(gr);
            const float z  = sigt(gz);
            const float n  = tanha(fmaf(r, gn, in));
            const float hn = fmaxf(0.0f, fmaf(z, h - n, n));

            hs[lt] = hn;
            yb[lt] = hn * wlin;
        }
        __syncthreads();

        // y head: warp 7 of each group reduces its batch (overlaps next matvec)
        if (!mainw) {
            const float* yb = grp ? y1 : y0;
            float s = yb[ly] + yb[ly + 32] + yb[ly + 64] + yb[ly + 96]
                    + ((ly + 128 < HID) ? yb[ly + 128] : 0.0f);
            s += __shfl_xor_sync(0xffffffffu, s, 16);
            s += __shfl_xor_sync(0xffffffffu, s, 8);
            s += __shfl_xor_sync(0xffffffffu, s, 4);
            s += __shfl_xor_sync(0xffffffffu, s, 2);
            s += __shfl_xor_sync(0xffffffffu, s, 1);
            if (ly == 0) (grp ? or1 : or0)[t] = s + bl;
        }
    }
}

extern "C" void kernel_launch(void* const* d_in, const int* in_sizes, int n_in,
                              void* d_out, int out_size) {
    const float* x    = (const float*)d_in[0];
    const float* Wih  = (const float*)d_in[1];
    const float* Whh  = (const float*)d_in[2];
    const float* bih  = (const float*)d_in[3];
    const float* bhh  = (const float*)d_in[4];
    const float* Wlin = (const float*)d_in[5];
    const float* blin = (const float*)d_in[6];
    float* out = (float*)d_out;

    const size_t smem_bytes = SMEM_FLOATS * sizeof(float);   // 155,200 B
    cudaFuncSetAttribute(gru_persistent,
                         cudaFuncAttributeMaxDynamicSharedMemorySize,
                         (int)smem_bytes);

    gru_persistent<<<128, NTH, smem_bytes>>>(x, Wih, Whh, bih, bhh, Wlin, blin, out);
}